// round 16
// baseline (speedup 1.0000x reference)
#include <cuda_runtime.h>

#define SEQ    4096
#define CHUNK  128
#define NCH    32              // SEQ/CHUNK
#define NT     512             // kernel2: 64 rows/block, 8 lanes/row
#define NT1    576             // kernel1: one block per batch
#define PER    19
#define VOCAB  10
#define NBIN   190             // VOCAB*PER
#define NMOM   570             // 3*NBIN

// scratch: per-chunk moments, then exclusive prefixes
__device__ float g_chnk[4][NCH][NMOM];
__device__ float g_pref[4][NCH][NMOM];

// fp32 Omega and its residual vs double 2*pi/19 (compile-time folded)
#define OM_F   0.3306939635357677f
#define OM_RES ((float)(0.3306939635357677 - (double)0.3306939635357677f))

// ---- kernel 1: per-batch prefix moments, parallel 3-phase (atomic-free) -----
__global__ __launch_bounds__(NT1)
void prefix_moments_kernel(const int* __restrict__ tokens)
{
    const int b   = blockIdx.x;
    const int tid = threadIdx.x;

    __shared__ float         d1Sh[SEQ];
    __shared__ unsigned char tokSh[SEQ];

    // Phase A: tokens + exact fp32-rope rounding error
    for (int j = tid; j < SEQ; j += NT1) {
        tokSh[j] = (unsigned char)tokens[b * SEQ + j];
        float jf = (float)j;
        float th = jf * OM_F;                        // reference's fp32 angle
        d1Sh[j] = -fmaf(jf, OM_F, -th) - jf * OM_RES; // th - j*Omega_exact
    }
    __syncthreads();

    // Phase B: 6080 independent (chunk, bin) partial moments (~7 LDS each)
    for (int idx = tid; idx < NCH * NBIN; idx += NT1) {
        const int c = idx / NBIN;
        const int k = idx - c * NBIN;
        const int t = k / PER, m = k - t * PER;
        const int cstart = c * CHUNK;
        int off = m - cstart % PER; if (off < 0) off += PER;
        float cnt = 0.f, s1 = 0.f, s2 = 0.f;
        #pragma unroll 4
        for (int j = cstart + off; j < cstart + CHUNK; j += PER) {
            if (tokSh[j] == t) {
                float d = d1Sh[j];
                cnt += 1.f; s1 += d; s2 = fmaf(d, d, s2);
            }
        }
        g_chnk[b][c][k]            = cnt;    // consecutive tid -> consecutive k
        g_chnk[b][c][NBIN + k]     = s1;     // (coalesced stores)
        g_chnk[b][c][2 * NBIN + k] = s2;
    }
    __syncthreads();   // block-wide visibility of g_chnk (same block reads next)

    // Phase C: exclusive scan over 32 chunks, one moment element per thread
    if (tid < NMOM) {
        float acc = 0.f;
        #pragma unroll 4
        for (int c = 0; c < NCH; ++c) {
            g_pref[b][c][tid] = acc;         // exclusive
            acc += g_chnk[b][c][tid];        // coalesced across threads
        }
    }
}

// ---- kernel 2: binned softmax + epilogue (UNCHANGED from measured 12.8us) ---
__global__ __launch_bounds__(NT)
void adder_model_kernel(const int* __restrict__ tokens,
                        const float* __restrict__ cptr,
                        float* __restrict__ out)
{
    const int gx     = blockIdx.x;
    const int chunk  = gx >> 1;
    const int half   = gx & 1;           // which 64-row half of the chunk
    const int b      = blockIdx.y;
    const int cstart = chunk * CHUNK;
    const int tid    = threadIdx.x;

    __shared__ float  momSh[NMOM];       // this chunk's exclusive prefix moments
    __shared__ float4 binA[NBIN];        // {U, W, ln2*S1, cnt}
    __shared__ float2 binB[NBIN];        // {0.5*ln2^2*S2, v_t}
    __shared__ float4 uwv[CHUNK];        // in-chunk {u_j, w_j, v_j, 0}
    __shared__ unsigned char tokSh[CHUNK];
    __shared__ float2 csTab[PER];        // (cos,sin)(Omega*m), corrected fp32

    const float cs = cptr[0];

    // verified literals (cross-checked c^2+s^2 = 1 to 1e-8)
    const float ATTN = 52.9176498f;      // AMPL/2
    const float cphi = -0.96520891f;     // cos(10.3*Omega)
    const float sphi = -0.26147994f;     // sin(10.3*Omega)
    const float RS2  = 0.70710678118f;
    const float L2E  = 1.44269504089f;
    const float LN2  = 0.69314718056f;

    // ---- residue trig table ----
    if (tid < PER) {
        float mf = (float)tid;
        float ph = mf * OM_F;
        float dd = fmaf(mf, OM_F, -ph) + mf * OM_RES;   // Omega*m - ph (tiny)
        float cp = cosf(ph), sp = sinf(ph);             // |ph| < 6: fast path
        csTab[tid] = make_float2(fmaf(-dd, sp, cp), fmaf(dd, cp, sp));
    }
    // ---- fetch this chunk's prefix moments (single coalesced read) ----
    for (int e = tid; e < NMOM; e += NT)
        momSh[e] = g_pref[b][chunk][e];
    __syncthreads();                     // csTab + momSh ready

    // ---- in-chunk exact table (2nd-order expansion of cos(theta_f32)) ----
    if (tid < CHUNK) {
        int   j = cstart + tid;
        int   t = tokens[b * SEQ + j];
        tokSh[tid] = (unsigned char)t;
        float d  = (float)t;
        float t0 = cs - d * d / cs, t1 = -d;
        float inv = rsqrtf((t0 * t0 + t1 * t1) * 0.5f + 1e-6f);
        float x0 = t0 * inv, x1 = t1 * inv;
        float s  = x0 * rsqrtf(x0 * x0 * 0.5f + 1e-6f);  // shared q/k norm scale
        float v  = x1 * (-22.0f * RS2) * cs;              // V_FACTOR * cs
        float jf = (float)j;
        float th = jf * OM_F;
        float d1 = -fmaf(jf, OM_F, -th) - jf * OM_RES;    // theta_f32 - j*Omega
        float2 cm = csTab[j % PER];
        float hd2 = 0.5f * d1 * d1;
        float c_ = fmaf(-d1, cm.y, cm.x) - hd2 * cm.x;    // cos(Om*m + d1)
        float s_ = fmaf( d1, cm.x, cm.y) - hd2 * cm.y;    // sin(Om*m + d1)
        uwv[tid] = make_float4(s * c_, s * s_, v, 0.f);
    }
    // ---- pack bins ----
    for (int k = tid; k < NBIN; k += NT) {
        int   t = k / PER, m = k - t * PER;
        float d  = (float)t;
        float t0 = cs - d * d / cs, t1 = -d;
        float inv = rsqrtf((t0 * t0 + t1 * t1) * 0.5f + 1e-6f);
        float x0 = t0 * inv, x1 = t1 * inv;
        float s  = x0 * rsqrtf(x0 * x0 * 0.5f + 1e-6f);
        float v  = x1 * (-22.0f * RS2) * cs;
        float2 cm = csTab[m];
        binA[k] = make_float4(s * cm.x, s * cm.y, LN2 * momSh[NBIN + k], momSh[k]);
        binB[k] = make_float2(0.5f * LN2 * LN2 * momSh[2 * NBIN + k], v);
    }
    __syncthreads();

    // ---- one row per octet (8 lanes); bins + tail split over 8 lanes ----
    const int oct  = tid >> 3;
    const int sub  = tid & 7;
    const int r    = half * 64 + oct;          // row in chunk (0..127)
    const int i    = cstart + r;
    const unsigned omask = 0xffu << ((tid & 31) & ~7);   // this octet's lanes

    float4 qi = uwv[r];
    float a2 = ATTN * fmaf(cphi, qi.x,  sphi * qi.y) * L2E;
    float b2 = ATTN * fmaf(cphi, qi.y, -sphi * qi.x) * L2E;
    float m2 = -1.41432f * sqrtf(a2 * a2 + b2 * b2) - 1e-3f;   // bound shift

    float den = 0.f, num = 0.f;
    #pragma unroll 4
    for (int k = sub; k < NBIN; k += 8) {
        float4 A  = binA[k];  float2 Bv = binB[k];
        float Bx  = fmaf(a2, A.x, fmaf(b2, A.y, m2));          // <= ~0 by bound
        float G   = fmaf(b2, A.x, -(a2 * A.y));
        float fac = fmaf(G, A.z, A.w);
        fac = fmaf(G * G, Bv.x, fac);
        float ef = exp2f(Bx) * fac;
        den += ef;
        num  = fmaf(ef, Bv.y, num);
    }
    for (int jl = sub; jl <= r; jl += 8) {                     // exact in-chunk tail
        float4 t4 = uwv[jl];
        float e = exp2f(fmaf(a2, t4.x, fmaf(b2, t4.y, m2)));
        den += e;
        num  = fmaf(e, t4.z, num);
    }
    den += __shfl_xor_sync(0xffffffffu, den, 1);
    num += __shfl_xor_sync(0xffffffffu, num, 1);
    den += __shfl_xor_sync(0xffffffffu, den, 2);
    num += __shfl_xor_sync(0xffffffffu, num, 2);
    den += __shfl_xor_sync(0xffffffffu, den, 4);
    num += __shfl_xor_sync(0xffffffffu, num, 4);

    if (den < 1e-20f) {
        // rare (rows < 19 of chunk 0): exact-max rescan split over the octet.
        // Octets may diverge within a warp -> octet-masked shfls only.
        float mx = -1e30f;
        for (int k = sub; k < NBIN; k += 8) {
            float4 A = binA[k];
            if (A.w > 0.f) mx = fmaxf(mx, fmaf(a2, A.x, b2 * A.y));
        }
        for (int jl = sub; jl <= r; jl += 8) {
            float4 t4 = uwv[jl];
            mx = fmaxf(mx, fmaf(a2, t4.x, b2 * t4.y));
        }
        mx = fmaxf(mx, __shfl_xor_sync(omask, mx, 1));
        mx = fmaxf(mx, __shfl_xor_sync(omask, mx, 2));
        mx = fmaxf(mx, __shfl_xor_sync(omask, mx, 4));

        den = 0.f; num = 0.f;
        for (int k = sub; k < NBIN; k += 8) {
            float4 A = binA[k];  float2 Bv = binB[k];
            float Bx  = fminf(fmaf(a2, A.x, b2 * A.y) - mx, 0.f);  // no inf*0
            float G   = fmaf(b2, A.x, -(a2 * A.y));
            float fac = fmaf(G, A.z, A.w);
            fac = fmaf(G * G, Bv.x, fac);
            float ef = exp2f(Bx) * fac;
            den += ef;
            num  = fmaf(ef, Bv.y, num);
        }
        for (int jl = sub; jl <= r; jl += 8) {
            float4 t4 = uwv[jl];
            float e = exp2f(fminf(fmaf(a2, t4.x, b2 * t4.y) - mx, 0.f));
            den += e;
            num  = fmaf(e, t4.z, num);
        }
        den += __shfl_xor_sync(omask, den, 1);
        num += __shfl_xor_sync(omask, num, 1);
        den += __shfl_xor_sync(omask, den, 2);
        num += __shfl_xor_sync(omask, num, 2);
        den += __shfl_xor_sync(omask, den, 4);
        num += __shfl_xor_sync(omask, num, 4);
    }
    const float o0 = num / den;       // attention output (only used component)

    // ---- fused epilogue (octet-redundant; writes split across 8 lanes) ----
    const float dq = (float)tokSh[r];
    float h0 = cs - dq * dq / cs;     // tab0[tok_i]
    float h1 = -dq + o0;              // tab1[tok_i] + attn
    float inv = rsqrtf((h0 * h0 + h1 * h1) * 0.5f + 1e-6f);
    float hn0 = h0 * inv, hn1 = h1 * inv;

    float aC = -12.032f * cs;
    float gc = 128.f * cs;
    float g0 = hn0 * aC + hn1 * gc;
    float g1 = hn0 * (aC - 128.f) + hn1 * gc;        // a - gc/cs = a - 128
    float sg0 = 1.f / (1.f + exp2f(-g0 * L2E));      // sigmoid via exp2
    float sg1 = 1.f / (1.f + exp2f(-g1 * L2E));
    h1 += (100.f / 256.f) * (g1 * sg1 - g0 * sg0) * hn0;

    float inv2 = rsqrtf((h0 * h0 + h1 * h1) * 0.5f + 1e-6f);
    float w0 = h0 * inv2 * (0.1f * cs * RS2);
    float w1 = h1 * inv2 * (-cs * 0.02f * RS2);

    float* orow = out + ((size_t)b * SEQ + i) * VOCAB;
    for (int d = sub; d < VOCAB; d += 8) {
        float dd = (float)d;
        orow[d] = fmaf(w0, cs - dd * dd / cs, w1 * (-dd));
    }
}

extern "C" void kernel_launch(void* const* d_in, const int* in_sizes, int n_in,
                              void* d_out, int out_size)
{
    const int*   tokens = (const int*)d_in[0];
    const float* c      = (const float*)d_in[1];
    int ntok = in_sizes[0];
    if (n_in >= 2 && in_sizes[0] == 1) {   // defensive input-order swap
        tokens = (const int*)d_in[1];
        c      = (const float*)d_in[0];
        ntok   = in_sizes[1];
    }
    int B = ntok / SEQ;                    // 4
    if (B > 4) B = 4;
    dim3 grid2(2 * NCH, B);
    prefix_moments_kernel<<<B, NT1>>>(tokens);
    adder_model_kernel   <<<grid2, NT>>>(tokens, c, (float*)d_out);
    (void)out_size;
}

// round 17
// speedup vs baseline: 1.4981x; 1.4981x over previous
#include <cuda_runtime.h>

#define SEQ    4096
#define CHUNK  128
#define NCH    32              // SEQ/CHUNK
#define NT     512             // kernel2: 64 rows/block, 8 lanes/row
#define NT1    192             // kernel1: one block per (chunk, batch)
#define PER    19
#define VOCAB  10
#define NBIN   190             // VOCAB*PER
#define NMOM   570             // 3*NBIN

// per-chunk bin moments: [batch][chunk][{cnt|s1|s2} x bin]
__device__ float g_chnk[4][NCH][NMOM];

// fp32 Omega and its residual vs double 2*pi/19 (compile-time folded)
#define OM_F   0.3306939635357677f
#define OM_RES ((float)(0.3306939635357677 - (double)0.3306939635357677f))

// ---- kernel 1: per-chunk moments, 128 wide blocks (atomic-free, fp32) -------
__global__ __launch_bounds__(NT1)
void chunk_moments_kernel(const int* __restrict__ tokens)
{
    const int chunk  = blockIdx.x;
    const int b      = blockIdx.y;
    const int cstart = chunk * CHUNK;
    const int tid    = threadIdx.x;

    __shared__ float         d1Sh[CHUNK];
    __shared__ unsigned char tokSh[CHUNK];

    if (tid < CHUNK) {
        int j = cstart + tid;
        tokSh[tid] = (unsigned char)tokens[b * SEQ + j];
        float jf = (float)j;
        float th = jf * OM_F;                        // reference's fp32 angle
        // d1 = th - j*Omega_exact, exact FMA rounding-error extraction
        d1Sh[tid] = -fmaf(jf, OM_F, -th) - jf * OM_RES;
    }
    __syncthreads();

    if (tid < NBIN) {
        const int t = tid / PER, m = tid - t * PER;
        float cnt = 0.f, s1 = 0.f, s2 = 0.f;
        int jl = m - (cstart % PER); if (jl < 0) jl += PER;
        #pragma unroll 4
        for (; jl < CHUNK; jl += PER) {
            if (tokSh[jl] == t) {
                float d = d1Sh[jl];
                cnt += 1.f; s1 += d; s2 = fmaf(d, d, s2);
            }
        }
        g_chnk[b][chunk][tid]            = cnt;
        g_chnk[b][chunk][NBIN + tid]     = s1;
        g_chnk[b][chunk][2 * NBIN + tid] = s2;
    }
}

// ---- kernel 2: prefix (MLP-parallel) + binned softmax + epilogue ------------
__global__ __launch_bounds__(NT)
void adder_model_kernel(const int* __restrict__ tokens,
                        const float* __restrict__ cptr,
                        float* __restrict__ out)
{
    const int gx     = blockIdx.x;
    const int chunk  = gx >> 1;
    const int half   = gx & 1;           // which 64-row half of the chunk
    const int b      = blockIdx.y;
    const int cstart = chunk * CHUNK;
    const int tid    = threadIdx.x;

    __shared__ float  momSh[NMOM];       // accumulated prefix moments
    __shared__ float4 binA[NBIN];        // {U, W, ln2*S1, cnt}
    __shared__ float2 binB[NBIN];        // {0.5*ln2^2*S2, v_t}
    __shared__ float4 uwv[CHUNK];        // in-chunk {u_j, w_j, v_j, 0}
    __shared__ unsigned char tokSh[CHUNK];
    __shared__ float2 csTab[PER];        // (cos,sin)(Omega*m), corrected fp32

    const float cs = cptr[0];

    // verified literals (cross-checked c^2+s^2 = 1 to 1e-8)
    const float ATTN = 52.9176498f;      // AMPL/2
    const float cphi = -0.96520891f;     // cos(10.3*Omega)
    const float sphi = -0.26147994f;     // sin(10.3*Omega)
    const float RS2  = 0.70710678118f;
    const float L2E  = 1.44269504089f;
    const float LN2  = 0.69314718056f;

    // ---- residue trig table ----
    if (tid < PER) {
        float mf = (float)tid;
        float ph = mf * OM_F;
        float dd = fmaf(mf, OM_F, -ph) + mf * OM_RES;   // Omega*m - ph (tiny)
        float cp = cosf(ph), sp = sinf(ph);             // |ph| < 6: fast path
        csTab[tid] = make_float2(fmaf(-dd, sp, cp), fmaf(dd, cp, sp));
    }
    // ---- prefix accumulate over chunks < chunk (independent coalesced LDGs) ----
    for (int e = tid; e < NMOM; e += NT) {
        float acc = 0.f;
        #pragma unroll 8
        for (int c = 0; c < chunk; ++c) acc += g_chnk[b][c][e];
        momSh[e] = acc;
    }
    __syncthreads();                     // csTab + momSh ready

    // ---- in-chunk exact table (2nd-order expansion of cos(theta_f32)) ----
    if (tid < CHUNK) {
        int   j = cstart + tid;
        int   t = tokens[b * SEQ + j];
        tokSh[tid] = (unsigned char)t;
        float d  = (float)t;
        float t0 = cs - d * d / cs, t1 = -d;
        float inv = rsqrtf((t0 * t0 + t1 * t1) * 0.5f + 1e-6f);
        float x0 = t0 * inv, x1 = t1 * inv;
        float s  = x0 * rsqrtf(x0 * x0 * 0.5f + 1e-6f);  // shared q/k norm scale
        float v  = x1 * (-22.0f * RS2) * cs;              // V_FACTOR * cs
        float jf = (float)j;
        float th = jf * OM_F;
        float d1 = -fmaf(jf, OM_F, -th) - jf * OM_RES;    // theta_f32 - j*Omega
        float2 cm = csTab[j % PER];
        float hd2 = 0.5f * d1 * d1;
        float c_ = fmaf(-d1, cm.y, cm.x) - hd2 * cm.x;    // cos(Om*m + d1)
        float s_ = fmaf( d1, cm.x, cm.y) - hd2 * cm.y;    // sin(Om*m + d1)
        uwv[tid] = make_float4(s * c_, s * s_, v, 0.f);
    }
    // ---- pack bins ----
    for (int k = tid; k < NBIN; k += NT) {
        int   t = k / PER, m = k - t * PER;
        float d  = (float)t;
        float t0 = cs - d * d / cs, t1 = -d;
        float inv = rsqrtf((t0 * t0 + t1 * t1) * 0.5f + 1e-6f);
        float x0 = t0 * inv, x1 = t1 * inv;
        float s  = x0 * rsqrtf(x0 * x0 * 0.5f + 1e-6f);
        float v  = x1 * (-22.0f * RS2) * cs;
        float2 cm = csTab[m];
        binA[k] = make_float4(s * cm.x, s * cm.y, LN2 * momSh[NBIN + k], momSh[k]);
        binB[k] = make_float2(0.5f * LN2 * LN2 * momSh[2 * NBIN + k], v);
    }
    __syncthreads();

    // ---- one row per octet (8 lanes); bins + tail split over 8 lanes ----
    const int oct  = tid >> 3;
    const int sub  = tid & 7;
    const int r    = half * 64 + oct;          // row in chunk (0..127)
    const int i    = cstart + r;
    const unsigned omask = 0xffu << ((tid & 31) & ~7);   // this octet's lanes

    float4 qi = uwv[r];
    float a2 = ATTN * fmaf(cphi, qi.x,  sphi * qi.y) * L2E;
    float b2 = ATTN * fmaf(cphi, qi.y, -sphi * qi.x) * L2E;
    float m2 = -1.41432f * sqrtf(a2 * a2 + b2 * b2) - 1e-3f;   // bound shift

    float den = 0.f, num = 0.f;
    #pragma unroll 4
    for (int k = sub; k < NBIN; k += 8) {
        float4 A  = binA[k];  float2 Bv = binB[k];
        float Bx  = fmaf(a2, A.x, fmaf(b2, A.y, m2));          // <= ~0 by bound
        float G   = fmaf(b2, A.x, -(a2 * A.y));
        float fac = fmaf(G, A.z, A.w);
        fac = fmaf(G * G, Bv.x, fac);
        float ef = exp2f(Bx) * fac;
        den += ef;
        num  = fmaf(ef, Bv.y, num);
    }
    for (int jl = sub; jl <= r; jl += 8) {                     // exact in-chunk tail
        float4 t4 = uwv[jl];
        float e = exp2f(fmaf(a2, t4.x, fmaf(b2, t4.y, m2)));
        den += e;
        num  = fmaf(e, t4.z, num);
    }
    den += __shfl_xor_sync(0xffffffffu, den, 1);
    num += __shfl_xor_sync(0xffffffffu, num, 1);
    den += __shfl_xor_sync(0xffffffffu, den, 2);
    num += __shfl_xor_sync(0xffffffffu, num, 2);
    den += __shfl_xor_sync(0xffffffffu, den, 4);
    num += __shfl_xor_sync(0xffffffffu, num, 4);

    if (den < 1e-20f) {
        // rare (rows < 19 of chunk 0): exact-max rescan split over the octet.
        // Octets may diverge within a warp -> octet-masked shfls only.
        float mx = -1e30f;
        for (int k = sub; k < NBIN; k += 8) {
            float4 A = binA[k];
            if (A.w > 0.f) mx = fmaxf(mx, fmaf(a2, A.x, b2 * A.y));
        }
        for (int jl = sub; jl <= r; jl += 8) {
            float4 t4 = uwv[jl];
            mx = fmaxf(mx, fmaf(a2, t4.x, b2 * t4.y));
        }
        mx = fmaxf(mx, __shfl_xor_sync(omask, mx, 1));
        mx = fmaxf(mx, __shfl_xor_sync(omask, mx, 2));
        mx = fmaxf(mx, __shfl_xor_sync(omask, mx, 4));

        den = 0.f; num = 0.f;
        for (int k = sub; k < NBIN; k += 8) {
            float4 A = binA[k];  float2 Bv = binB[k];
            float Bx  = fminf(fmaf(a2, A.x, b2 * A.y) - mx, 0.f);  // no inf*0
            float G   = fmaf(b2, A.x, -(a2 * A.y));
            float fac = fmaf(G, A.z, A.w);
            fac = fmaf(G * G, Bv.x, fac);
            float ef = exp2f(Bx) * fac;
            den += ef;
            num  = fmaf(ef, Bv.y, num);
        }
        for (int jl = sub; jl <= r; jl += 8) {
            float4 t4 = uwv[jl];
            float e = exp2f(fminf(fmaf(a2, t4.x, b2 * t4.y) - mx, 0.f));
            den += e;
            num  = fmaf(e, t4.z, num);
        }
        den += __shfl_xor_sync(omask, den, 1);
        num += __shfl_xor_sync(omask, num, 1);
        den += __shfl_xor_sync(omask, den, 2);
        num += __shfl_xor_sync(omask, num, 2);
        den += __shfl_xor_sync(omask, den, 4);
        num += __shfl_xor_sync(omask, num, 4);
    }
    const float o0 = num / den;       // attention output (only used component)

    // ---- fused epilogue (octet-redundant; writes split across 8 lanes) ----
    const float dq = (float)tokSh[r];
    float h0 = cs - dq * dq / cs;     // tab0[tok_i]
    float h1 = -dq + o0;              // tab1[tok_i] + attn
    float inv = rsqrtf((h0 * h0 + h1 * h1) * 0.5f + 1e-6f);
    float hn0 = h0 * inv, hn1 = h1 * inv;

    float aC = -12.032f * cs;
    float gc = 128.f * cs;
    float g0 = hn0 * aC + hn1 * gc;
    float g1 = hn0 * (aC - 128.f) + hn1 * gc;        // a - gc/cs = a - 128
    float sg0 = 1.f / (1.f + exp2f(-g0 * L2E));      // sigmoid via exp2
    float sg1 = 1.f / (1.f + exp2f(-g1 * L2E));
    h1 += (100.f / 256.f) * (g1 * sg1 - g0 * sg0) * hn0;

    float inv2 = rsqrtf((h0 * h0 + h1 * h1) * 0.5f + 1e-6f);
    float w0 = h0 * inv2 * (0.1f * cs * RS2);
    float w1 = h1 * inv2 * (-cs * 0.02f * RS2);

    float* orow = out + ((size_t)b * SEQ + i) * VOCAB;
    for (int d = sub; d < VOCAB; d += 8) {
        float dd = (float)d;
        orow[d] = fmaf(w0, cs - dd * dd / cs, w1 * (-dd));
    }
}

extern "C" void kernel_launch(void* const* d_in, const int* in_sizes, int n_in,
                              void* d_out, int out_size)
{
    const int*   tokens = (const int*)d_in[0];
    const float* c      = (const float*)d_in[1];
    int ntok = in_sizes[0];
    if (n_in >= 2 && in_sizes[0] == 1) {   // defensive input-order swap
        tokens = (const int*)d_in[1];
        c      = (const float*)d_in[0];
        ntok   = in_sizes[1];
    }
    int B = ntok / SEQ;                    // 4
    if (B > 4) B = 4;
    dim3 grid1(NCH, B);
    dim3 grid2(2 * NCH, B);
    chunk_moments_kernel<<<grid1, NT1>>>(tokens);
    adder_model_kernel  <<<grid2, NT >>>(tokens, c, (float*)d_out);
    (void)out_size;
}